// round 12
// baseline (speedup 1.0000x reference)
#include <cuda_runtime.h>
#include <math.h>

// MoE router: logits = x @ W^T  ([16384,2048] x [2048,8]), top-2 + softmax.
// Output layout (fp32): [indices 16384*2][gates 16384*2][logits 16384*8].
//
// R9's key insight kept: W lives in shared memory, so the per-SM L1tex
// global-load FIFO carries only the x stream. New lever: a THIRD block per
// SM (launch_bounds(256,3), 64KB smem x 3 = 192KB < 227KB) -> 24 warps/SM.
// More warps previously hurt only because W-loads contended in the global
// FIFO; with W on the LDS pipe the extra warps add pure in-flight DRAM
// bytes. Inner loop is the low-register unroll-1 shape (~64 regs) so the
// 85-reg cap at occupancy 3 never spills.

#define DDIM 2048
#define NEXP 8
#define TGRP 4
#define CHUNKS (DDIM / 128)       // 16 chunks of 128 floats (4 per lane)
#define W_FLOATS (NEXP * DDIM)    // 16384
#define SMEM_BYTES (W_FLOATS * 4) // 65536
#define NBLOCK 444

__global__ __launch_bounds__(256, 3)
void router_kernel(const float* __restrict__ x,
                   const float* __restrict__ w,
                   float* __restrict__ out,
                   int n_tokens, int groups_total)
{
    extern __shared__ float ws[];   // [NEXP][DDIM]

    // Cooperative W load: 4096 float4s over 256 threads = 16 each.
    {
        const float4* wsrc = reinterpret_cast<const float4*>(w);
        float4* wdst = reinterpret_cast<float4*>(ws);
        #pragma unroll
        for (int i = 0; i < W_FLOATS / 4 / 256; i++)
            wdst[threadIdx.x + i * 256] = wsrc[threadIdx.x + i * 256];
    }
    __syncthreads();

    const int lane  = threadIdx.x & 31;
    const int warp  = (blockIdx.x * blockDim.x + threadIdx.x) >> 5;
    const int nwarp = (gridDim.x * blockDim.x) >> 5;

    float* out_idx    = out;
    float* out_gate   = out + (size_t)n_tokens * 2;
    float* out_logits = out + (size_t)n_tokens * 4;

    const float* wsl = ws + lane * 4;

    for (int g = warp; g < groups_total; g += nwarp) {
        const int tok0 = g * TGRP;
        const float* xp = x + (size_t)tok0 * DDIM + lane * 4;

        float acc[TGRP][NEXP];
        #pragma unroll
        for (int t = 0; t < TGRP; t++)
            #pragma unroll
            for (int e = 0; e < NEXP; e++)
                acc[t][e] = 0.0f;

        #pragma unroll 1
        for (int c = 0; c < CHUNKS; c++) {
            float4 xv[TGRP];
            #pragma unroll
            for (int t = 0; t < TGRP; t++)
                xv[t] = *reinterpret_cast<const float4*>(
                            xp + (size_t)t * DDIM + c * 128);
            #pragma unroll
            for (int e = 0; e < NEXP; e++) {
                float4 wv = *reinterpret_cast<const float4*>(wsl + e * DDIM + c * 128);
                #pragma unroll
                for (int t = 0; t < TGRP; t++) {
                    acc[t][e] = fmaf(xv[t].x, wv.x,
                                fmaf(xv[t].y, wv.y,
                                fmaf(xv[t].z, wv.z,
                                fmaf(xv[t].w, wv.w, acc[t][e]))));
                }
            }
        }

        // Full butterfly reduction: every lane ends with the complete sums.
        #pragma unroll
        for (int t = 0; t < TGRP; t++) {
            #pragma unroll
            for (int e = 0; e < NEXP; e++) {
                float v = acc[t][e];
                v += __shfl_xor_sync(0xffffffffu, v, 16);
                v += __shfl_xor_sync(0xffffffffu, v, 8);
                v += __shfl_xor_sync(0xffffffffu, v, 4);
                v += __shfl_xor_sync(0xffffffffu, v, 2);
                v += __shfl_xor_sync(0xffffffffu, v, 1);
                acc[t][e] = v;
            }
        }

        if (lane < TGRP) {
            const int tok = tok0 + lane;
            // Predicated token select (no dynamic register indexing).
            float v[NEXP];
            #pragma unroll
            for (int e = 0; e < NEXP; e++) {
                float s = acc[0][e];
                if (lane == 1) s = acc[1][e];
                if (lane == 2) s = acc[2][e];
                if (lane == 3) s = acc[3][e];
                v[e] = s;
            }

            // logits (two 16B stores)
            *reinterpret_cast<float4*>(out_logits + (size_t)tok * NEXP) =
                make_float4(v[0], v[1], v[2], v[3]);
            *reinterpret_cast<float4*>(out_logits + (size_t)tok * NEXP + 4) =
                make_float4(v[4], v[5], v[6], v[7]);

            // top-2 (ties -> lower index, matching jax.lax.top_k)
            int i0 = 0; float v0 = v[0];
            #pragma unroll
            for (int e = 1; e < NEXP; e++)
                if (v[e] > v0) { v0 = v[e]; i0 = e; }
            int i1 = -1; float v1 = -INFINITY;
            #pragma unroll
            for (int e = 0; e < NEXP; e++)
                if (e != i0 && v[e] > v1) { v1 = v[e]; i1 = e; }

            // softmax over [v0, v1] with v0 = max
            float ex = __expf(v1 - v0);
            float g0 = 1.0f / (1.0f + ex);
            float g1 = ex * g0;

            *reinterpret_cast<float2*>(out_idx  + (size_t)tok * 2) =
                make_float2((float)i0, (float)i1);
            *reinterpret_cast<float2*>(out_gate + (size_t)tok * 2) =
                make_float2(g0, g1);
        }
    }
}

extern "C" void kernel_launch(void* const* d_in, const int* in_sizes, int n_in,
                              void* d_out, int out_size)
{
    const float* x = (const float*)d_in[0];
    const float* w = (const float*)d_in[1];
    float* out = (float*)d_out;

    const int n_tokens = in_sizes[0] / DDIM;     // 16384
    const int groups   = n_tokens / TGRP;        // 4096

    cudaFuncSetAttribute(router_kernel,
                         cudaFuncAttributeMaxDynamicSharedMemorySize,
                         SMEM_BYTES);

    router_kernel<<<NBLOCK, 256, SMEM_BYTES>>>(x, w, out, n_tokens, groups);
}

// round 13
// speedup vs baseline: 1.1534x; 1.1534x over previous
#include <cuda_runtime.h>
#include <math.h>

// MoE router: logits = x @ W^T  ([16384,2048] x [2048,8]), top-2 + softmax.
// Output layout (fp32): [indices 16384*2][gates 16384*2][logits 16384*8].
//
// R11 base (W in shared memory -> global-load FIFO carries only x; 296x256,
// 2 blocks/SM) with prefetch DISTANCE 2: three rotating register buffers so
// that while chunk c is computed, the LDG.128s for chunks c+1 and c+2 are
// both outstanding (~4KB/warp in flight; 16 warps/SM -> ~64KB/SM, clearing
// the ~33KB Little's-law bar that capped R9/R11 at 58% DRAM).

#define DDIM 2048
#define NEXP 8
#define TGRP 4
#define CHUNKS (DDIM / 128)       // 16 chunks of 128 floats (4 per lane)
#define W_FLOATS (NEXP * DDIM)    // 16384
#define SMEM_BYTES (W_FLOATS * 4) // 65536
#define NBLOCK 296

__global__ __launch_bounds__(256, 2)
void router_kernel(const float* __restrict__ x,
                   const float* __restrict__ w,
                   float* __restrict__ out,
                   int n_tokens, int groups_total)
{
    extern __shared__ float ws[];   // [NEXP][DDIM]

    // Cooperative W load: 4096 float4s over 256 threads = 16 each.
    {
        const float4* wsrc = reinterpret_cast<const float4*>(w);
        float4* wdst = reinterpret_cast<float4*>(ws);
        #pragma unroll
        for (int i = 0; i < W_FLOATS / 4 / 256; i++)
            wdst[threadIdx.x + i * 256] = wsrc[threadIdx.x + i * 256];
    }
    __syncthreads();

    const int lane  = threadIdx.x & 31;
    const int warp  = (blockIdx.x * blockDim.x + threadIdx.x) >> 5;
    const int nwarp = (gridDim.x * blockDim.x) >> 5;

    float* out_idx    = out;
    float* out_gate   = out + (size_t)n_tokens * 2;
    float* out_logits = out + (size_t)n_tokens * 4;

    const float* wsl = ws + lane * 4;

    for (int g = warp; g < groups_total; g += nwarp) {
        const int tok0 = g * TGRP;
        const float* xp = x + (size_t)tok0 * DDIM + lane * 4;

        float acc[TGRP][NEXP];
        #pragma unroll
        for (int t = 0; t < TGRP; t++)
            #pragma unroll
            for (int e = 0; e < NEXP; e++)
                acc[t][e] = 0.0f;

        // Prefetch-distance-2 pipeline: buffers b0 (compute), b1, b2 (in
        // flight). Prologue loads chunks 0 and 1.
        float4 b0[TGRP], b1[TGRP], b2[TGRP];
        #pragma unroll
        for (int t = 0; t < TGRP; t++)
            b0[t] = *reinterpret_cast<const float4*>(xp + (size_t)t * DDIM);
        #pragma unroll
        for (int t = 0; t < TGRP; t++)
            b1[t] = *reinterpret_cast<const float4*>(xp + (size_t)t * DDIM + 128);

        #pragma unroll 1
        for (int c = 0; c < CHUNKS; c++) {
            // Issue loads for chunk c+2 before computing chunk c.
            if (c + 2 < CHUNKS) {
                #pragma unroll
                for (int t = 0; t < TGRP; t++)
                    b2[t] = *reinterpret_cast<const float4*>(
                        xp + (size_t)t * DDIM + (c + 2) * 128);
            }
            #pragma unroll
            for (int e = 0; e < NEXP; e++) {
                float4 wv = *reinterpret_cast<const float4*>(wsl + e * DDIM + c * 128);
                #pragma unroll
                for (int t = 0; t < TGRP; t++) {
                    acc[t][e] = fmaf(b0[t].x, wv.x,
                                fmaf(b0[t].y, wv.y,
                                fmaf(b0[t].z, wv.z,
                                fmaf(b0[t].w, wv.w, acc[t][e]))));
                }
            }
            // Rotate buffers.
            #pragma unroll
            for (int t = 0; t < TGRP; t++) {
                b0[t] = b1[t];
                b1[t] = b2[t];
            }
        }

        // Full butterfly reduction: every lane ends with the complete sums.
        #pragma unroll
        for (int t = 0; t < TGRP; t++) {
            #pragma unroll
            for (int e = 0; e < NEXP; e++) {
                float v = acc[t][e];
                v += __shfl_xor_sync(0xffffffffu, v, 16);
                v += __shfl_xor_sync(0xffffffffu, v, 8);
                v += __shfl_xor_sync(0xffffffffu, v, 4);
                v += __shfl_xor_sync(0xffffffffu, v, 2);
                v += __shfl_xor_sync(0xffffffffu, v, 1);
                acc[t][e] = v;
            }
        }

        if (lane < TGRP) {
            const int tok = tok0 + lane;
            // Predicated token select (no dynamic register indexing).
            float v[NEXP];
            #pragma unroll
            for (int e = 0; e < NEXP; e++) {
                float s = acc[0][e];
                if (lane == 1) s = acc[1][e];
                if (lane == 2) s = acc[2][e];
                if (lane == 3) s = acc[3][e];
                v[e] = s;
            }

            // logits (two 16B stores)
            *reinterpret_cast<float4*>(out_logits + (size_t)tok * NEXP) =
                make_float4(v[0], v[1], v[2], v[3]);
            *reinterpret_cast<float4*>(out_logits + (size_t)tok * NEXP + 4) =
                make_float4(v[4], v[5], v[6], v[7]);

            // top-2 (ties -> lower index, matching jax.lax.top_k)
            int i0 = 0; float v0 = v[0];
            #pragma unroll
            for (int e = 1; e < NEXP; e++)
                if (v[e] > v0) { v0 = v[e]; i0 = e; }
            int i1 = -1; float v1 = -INFINITY;
            #pragma unroll
            for (int e = 0; e < NEXP; e++)
                if (e != i0 && v[e] > v1) { v1 = v[e]; i1 = e; }

            // softmax over [v0, v1] with v0 = max
            float ex = __expf(v1 - v0);
            float g0 = 1.0f / (1.0f + ex);
            float g1 = ex * g0;

            *reinterpret_cast<float2*>(out_idx  + (size_t)tok * 2) =
                make_float2((float)i0, (float)i1);
            *reinterpret_cast<float2*>(out_gate + (size_t)tok * 2) =
                make_float2(g0, g1);
        }
    }
}

extern "C" void kernel_launch(void* const* d_in, const int* in_sizes, int n_in,
                              void* d_out, int out_size)
{
    const float* x = (const float*)d_in[0];
    const float* w = (const float*)d_in[1];
    float* out = (float*)d_out;

    const int n_tokens = in_sizes[0] / DDIM;     // 16384
    const int groups   = n_tokens / TGRP;        // 4096

    cudaFuncSetAttribute(router_kernel,
                         cudaFuncAttributeMaxDynamicSharedMemorySize,
                         SMEM_BYTES);

    router_kernel<<<NBLOCK, 256, SMEM_BYTES>>>(x, w, out, n_tokens, groups);
}

// round 14
// speedup vs baseline: 1.2391x; 1.0743x over previous
#include <cuda_runtime.h>
#include <math.h>
#include <stdint.h>

// MoE router: logits = x @ W^T  ([16384,2048] x [2048,8]), top-2 + softmax.
// Output layout (fp32): [indices 16384*2][gates 16384*2][logits 16384*8].
//
// W lives in shared memory (LDS pipe) -- proven in R9. x is now streamed via
// cp.async (LDGSTS): a 4-stage per-warp smem pipeline keeps ~6KB/warp of
// DRAM reads in flight with ZERO destination registers and no stall until
// wait_group. 16 warps/SM x 6KB = 96KB/SM outstanding, far above the ~33KB
// Little's-law requirement that register-based prefetch (R11-R13) could
// never reach. One 512-thread block per SM; smem = 64KB W + 128KB x = 192KB.

#define DDIM 2048
#define NEXP 8
#define TGRP 4
#define CHUNKS (DDIM / 128)        // 16 chunks of 128 floats (4 per lane)
#define W_FLOATS (NEXP * DDIM)     // 16384
#define NWARP 16
#define THREADS (NWARP * 32)
#define NSTAGE 4
#define STAGE_FLOATS (TGRP * 128)  // 512 floats = 2KB
#define XBUF_FLOATS (NWARP * NSTAGE * STAGE_FLOATS)
#define SMEM_BYTES ((W_FLOATS + XBUF_FLOATS) * 4)   // 64KB + 128KB = 192KB
#define NBLOCK 148

__device__ __forceinline__ void cp_async16(uint32_t dst, const float* src) {
    asm volatile("cp.async.cg.shared.global [%0], [%1], 16;"
                 :: "r"(dst), "l"(src));
}
__device__ __forceinline__ void cp_commit() {
    asm volatile("cp.async.commit_group;");
}
__device__ __forceinline__ void cp_wait3() {
    asm volatile("cp.async.wait_group 3;");
}

__global__ __launch_bounds__(THREADS, 1)
void router_kernel(const float* __restrict__ x,
                   const float* __restrict__ w,
                   float* __restrict__ out,
                   int n_tokens, int groups_total)
{
    extern __shared__ float smem[];
    float* ws = smem;                       // [NEXP][DDIM]
    const int lane = threadIdx.x & 31;
    const int wid  = threadIdx.x >> 5;

    // Cooperative W load: 4096 float4s over 512 threads = 8 each.
    {
        const float4* wsrc = reinterpret_cast<const float4*>(w);
        float4* wdst = reinterpret_cast<float4*>(ws);
        #pragma unroll
        for (int i = 0; i < W_FLOATS / 4 / THREADS; i++)
            wdst[threadIdx.x + i * THREADS] = wsrc[threadIdx.x + i * THREADS];
    }
    __syncthreads();

    float* xbuf = smem + W_FLOATS + wid * (NSTAGE * STAGE_FLOATS);
    const uint32_t xbuf_u32 =
        (uint32_t)__cvta_generic_to_shared(xbuf) + lane * 16;

    const int warp  = blockIdx.x * NWARP + wid;
    const int nwarp = gridDim.x * NWARP;

    float* out_idx    = out;
    float* out_gate   = out + (size_t)n_tokens * 2;
    float* out_logits = out + (size_t)n_tokens * 4;

    const float* wsl = ws + lane * 4;

    for (int g = warp; g < groups_total; g += nwarp) {
        const int tok0 = g * TGRP;
        const float* xp = x + (size_t)tok0 * DDIM + lane * 4;

        float acc[TGRP][NEXP];
        #pragma unroll
        for (int t = 0; t < TGRP; t++)
            #pragma unroll
            for (int e = 0; e < NEXP; e++)
                acc[t][e] = 0.0f;

        // Prologue: issue chunks 0..NSTAGE-1, one commit group each.
        #pragma unroll
        for (int c = 0; c < NSTAGE; c++) {
            #pragma unroll
            for (int t = 0; t < TGRP; t++)
                cp_async16(xbuf_u32 + (c * STAGE_FLOATS + t * 128) * 4,
                           xp + (size_t)t * DDIM + c * 128);
            cp_commit();
        }

        #pragma unroll 1
        for (int c = 0; c < CHUNKS; c++) {
            cp_wait3();   // <=3 groups pending -> chunk c's group complete
            const int s = c & (NSTAGE - 1);
            const float* stage = xbuf + s * STAGE_FLOATS;

            float4 xv[TGRP];
            #pragma unroll
            for (int t = 0; t < TGRP; t++)
                xv[t] = *reinterpret_cast<const float4*>(stage + t * 128 + lane * 4);

            #pragma unroll
            for (int e = 0; e < NEXP; e++) {
                float4 wv = *reinterpret_cast<const float4*>(wsl + e * DDIM + c * 128);
                #pragma unroll
                for (int t = 0; t < TGRP; t++) {
                    acc[t][e] = fmaf(xv[t].x, wv.x,
                                fmaf(xv[t].y, wv.y,
                                fmaf(xv[t].z, wv.z,
                                fmaf(xv[t].w, wv.w, acc[t][e]))));
                }
            }

            // Refill this stage with chunk c+NSTAGE (empty commit at tail
            // keeps the wait_group count invariant).
            if (c + NSTAGE < CHUNKS) {
                #pragma unroll
                for (int t = 0; t < TGRP; t++)
                    cp_async16(xbuf_u32 + (s * STAGE_FLOATS + t * 128) * 4,
                               xp + (size_t)t * DDIM + (c + NSTAGE) * 128);
            }
            cp_commit();
        }

        // Full butterfly reduction: every lane ends with the complete sums.
        #pragma unroll
        for (int t = 0; t < TGRP; t++) {
            #pragma unroll
            for (int e = 0; e < NEXP; e++) {
                float v = acc[t][e];
                v += __shfl_xor_sync(0xffffffffu, v, 16);
                v += __shfl_xor_sync(0xffffffffu, v, 8);
                v += __shfl_xor_sync(0xffffffffu, v, 4);
                v += __shfl_xor_sync(0xffffffffu, v, 2);
                v += __shfl_xor_sync(0xffffffffu, v, 1);
                acc[t][e] = v;
            }
        }

        if (lane < TGRP) {
            const int tok = tok0 + lane;
            // Predicated token select (no dynamic register indexing).
            float v[NEXP];
            #pragma unroll
            for (int e = 0; e < NEXP; e++) {
                float s = acc[0][e];
                if (lane == 1) s = acc[1][e];
                if (lane == 2) s = acc[2][e];
                if (lane == 3) s = acc[3][e];
                v[e] = s;
            }

            // logits (two 16B stores)
            *reinterpret_cast<float4*>(out_logits + (size_t)tok * NEXP) =
                make_float4(v[0], v[1], v[2], v[3]);
            *reinterpret_cast<float4*>(out_logits + (size_t)tok * NEXP + 4) =
                make_float4(v[4], v[5], v[6], v[7]);

            // top-2 (ties -> lower index, matching jax.lax.top_k)
            int i0 = 0; float v0 = v[0];
            #pragma unroll
            for (int e = 1; e < NEXP; e++)
                if (v[e] > v0) { v0 = v[e]; i0 = e; }
            int i1 = -1; float v1 = -INFINITY;
            #pragma unroll
            for (int e = 0; e < NEXP; e++)
                if (e != i0 && v[e] > v1) { v1 = v[e]; i1 = e; }

            // softmax over [v0, v1] with v0 = max
            float ex = __expf(v1 - v0);
            float g0 = 1.0f / (1.0f + ex);
            float g1 = ex * g0;

            *reinterpret_cast<float2*>(out_idx  + (size_t)tok * 2) =
                make_float2((float)i0, (float)i1);
            *reinterpret_cast<float2*>(out_gate + (size_t)tok * 2) =
                make_float2(g0, g1);
        }
    }
}

extern "C" void kernel_launch(void* const* d_in, const int* in_sizes, int n_in,
                              void* d_out, int out_size)
{
    const float* x = (const float*)d_in[0];
    const float* w = (const float*)d_in[1];
    float* out = (float*)d_out;

    const int n_tokens = in_sizes[0] / DDIM;     // 16384
    const int groups   = n_tokens / TGRP;        // 4096

    cudaFuncSetAttribute(router_kernel,
                         cudaFuncAttributeMaxDynamicSharedMemorySize,
                         SMEM_BYTES);

    router_kernel<<<NBLOCK, THREADS, SMEM_BYTES>>>(x, w, out, n_tokens, groups);
}

// round 15
// speedup vs baseline: 1.4097x; 1.1377x over previous
#include <cuda_runtime.h>
#include <math.h>
#include <stdint.h>

// MoE router: logits = x @ W^T  ([16384,2048] x [2048,8]), top-2 + softmax.
// Output layout (fp32): [indices 16384*2][gates 16384*2][logits 16384*8].
//
// Diagnosis after R9-R14 (three prefetch mechanisms all plateau at 58%
// DRAM): the stall is the GROUP-BOUNDARY bubble (epilogue + next-group load
// ramp, aligned across warps), not in-flight depth. This kernel:
//   1. keeps the cp.async stream CONTINUOUS across groups (refill for
//      chunks c>=12 targets the next group's rows -> 4 stages in flight
//      through every epilogue),
//   2. replaces the 160-shfl butterfly with a 31-shfl tree reduction
//      (result: lane v holds logit(token v>>3, expert v&7)),
//   3. stores logits with one coalesced STG.32 per lane.
// W stays in shared memory (LDS pipe; global FIFO carries only x).

#define DDIM 2048
#define NEXP 8
#define TGRP 4
#define CHUNKS (DDIM / 128)        // 16 chunks of 128 floats (4 per lane)
#define W_FLOATS (NEXP * DDIM)     // 16384
#define NWARP 16
#define THREADS (NWARP * 32)
#define NSTAGE 4
#define STAGE_FLOATS (TGRP * 128)  // 512 floats = 2KB
#define XBUF_FLOATS (NWARP * NSTAGE * STAGE_FLOATS)
#define SMEM_BYTES ((W_FLOATS + XBUF_FLOATS) * 4)   // 64KB + 128KB = 192KB
#define NBLOCK 148

__device__ __forceinline__ void cp_async16(uint32_t dst, const float* src) {
    asm volatile("cp.async.cg.shared.global [%0], [%1], 16;"
                 :: "r"(dst), "l"(src));
}
__device__ __forceinline__ void cp_commit() {
    asm volatile("cp.async.commit_group;");
}
__device__ __forceinline__ void cp_wait3() {
    asm volatile("cp.async.wait_group 3;");
}

__global__ __launch_bounds__(THREADS, 1)
void router_kernel(const float* __restrict__ x,
                   const float* __restrict__ w,
                   float* __restrict__ out,
                   int n_tokens, int groups_total)
{
    extern __shared__ float smem[];
    float* ws = smem;                       // [NEXP][DDIM]
    const int lane = threadIdx.x & 31;
    const int wid  = threadIdx.x >> 5;

    // Cooperative W load: 4096 float4s over 512 threads = 8 each.
    {
        const float4* wsrc = reinterpret_cast<const float4*>(w);
        float4* wdst = reinterpret_cast<float4*>(ws);
        #pragma unroll
        for (int i = 0; i < W_FLOATS / 4 / THREADS; i++)
            wdst[threadIdx.x + i * THREADS] = wsrc[threadIdx.x + i * THREADS];
    }
    __syncthreads();

    float* xbuf = smem + W_FLOATS + wid * (NSTAGE * STAGE_FLOATS);
    const uint32_t xbuf_u32 =
        (uint32_t)__cvta_generic_to_shared(xbuf) + lane * 16;

    // Warp-major group assignment: spreads multi-group warps over all SMs.
    const int gw      = wid * NBLOCK + (int)blockIdx.x;
    const int gstride = NBLOCK * NWARP;
    const int ngroups = (gw < groups_total)
                      ? (groups_total - 1 - gw) / gstride + 1 : 0;

    float* out_idx    = out;
    float* out_gate   = out + (size_t)n_tokens * 2;
    float* out_logits = out + (size_t)n_tokens * 4;

    const float* wsl = ws + lane * 4;

    if (ngroups == 0) return;

    // Pipeline prologue (once): chunks 0..3 of the first group.
    {
        const float* xp0 = x + (size_t)(gw * TGRP) * DDIM + lane * 4;
        #pragma unroll
        for (int c = 0; c < NSTAGE; c++) {
            #pragma unroll
            for (int t = 0; t < TGRP; t++)
                cp_async16(xbuf_u32 + (c * STAGE_FLOATS + t * 128) * 4,
                           xp0 + (size_t)t * DDIM + c * 128);
            cp_commit();
        }
    }

    for (int k = 0; k < ngroups; k++) {
        const int g    = gw + k * gstride;
        const int tok0 = g * TGRP;
        const float* xp = x + (size_t)tok0 * DDIM + lane * 4;
        const bool has_next = (k + 1 < ngroups);
        const float* xp_n = has_next
            ? x + (size_t)((g + gstride) * TGRP) * DDIM + lane * 4 : xp;

        float acc[TGRP][NEXP];
        #pragma unroll
        for (int t = 0; t < TGRP; t++)
            #pragma unroll
            for (int e = 0; e < NEXP; e++)
                acc[t][e] = 0.0f;

        #pragma unroll
        for (int c = 0; c < CHUNKS; c++) {
            cp_wait3();   // <=3 groups pending -> stream chunk for c complete
            const float* stage = xbuf + (c & (NSTAGE - 1)) * STAGE_FLOATS;

            float4 xv[TGRP];
            #pragma unroll
            for (int t = 0; t < TGRP; t++)
                xv[t] = *reinterpret_cast<const float4*>(stage + t * 128 + lane * 4);

            #pragma unroll
            for (int e = 0; e < NEXP; e++) {
                float4 wv = *reinterpret_cast<const float4*>(wsl + e * DDIM + c * 128);
                #pragma unroll
                for (int t = 0; t < TGRP; t++) {
                    acc[t][e] = fmaf(xv[t].x, wv.x,
                                fmaf(xv[t].y, wv.y,
                                fmaf(xv[t].z, wv.z,
                                fmaf(xv[t].w, wv.w, acc[t][e]))));
                }
            }

            // Continuous refill: chunk c+4 of the stream. For c>=12 that is
            // the NEXT group's chunk c-12, keeping DRAM busy through the
            // epilogue. Empty commits at the global tail are legal.
            const uint32_t sdst =
                xbuf_u32 + ((c & (NSTAGE - 1)) * STAGE_FLOATS) * 4;
            if (c < CHUNKS - NSTAGE) {
                #pragma unroll
                for (int t = 0; t < TGRP; t++)
                    cp_async16(sdst + t * 128 * 4,
                               xp + (size_t)t * DDIM + (c + NSTAGE) * 128);
            } else if (has_next) {
                #pragma unroll
                for (int t = 0; t < TGRP; t++)
                    cp_async16(sdst + t * 128 * 4,
                               xp_n + (size_t)t * DDIM + (c - (CHUNKS - NSTAGE)) * 128);
            }
            cp_commit();
        }

        // ---- Epilogue (next group's loads already in flight) ----
        // Tree multi-value reduction: 31 shfl instead of 160.
        // val index v = t*8+e; after 5 stages lane L's val[0] = sum of
        // value L over all lanes.
        float val[32];
        #pragma unroll
        for (int t = 0; t < TGRP; t++)
            #pragma unroll
            for (int e = 0; e < NEXP; e++)
                val[t * NEXP + e] = acc[t][e];

        #pragma unroll
        for (int i = 0; i < 5; i++) {
            const int off = 16 >> i;
            const int n   = 16 >> i;
            const bool up = (lane & off) != 0;
            #pragma unroll
            for (int j = 0; j < n; j++) {
                float keep = up ? val[j + n] : val[j];
                float send = up ? val[j]     : val[j + n];
                float recv = __shfl_xor_sync(0xffffffffu, send, off);
                val[j] = keep + recv;
            }
        }
        const float logit = val[0];   // logit(token tok0 + (lane>>3), expert lane&7)

        // Coalesced logits store: 32 contiguous floats, one per lane.
        out_logits[(size_t)tok0 * NEXP + lane] = logit;

        // Gather this token's 8 logits (token = lane & 3 for lanes 0..3).
        float le[NEXP];
        const int tsel = lane & 3;
        #pragma unroll
        for (int e = 0; e < NEXP; e++)
            le[e] = __shfl_sync(0xffffffffu, logit, tsel * NEXP + e);

        if (lane < TGRP) {
            const int tok = tok0 + lane;

            // top-2 (ties -> lower index, matching jax.lax.top_k)
            int i0 = 0; float v0 = le[0];
            #pragma unroll
            for (int e = 1; e < NEXP; e++)
                if (le[e] > v0) { v0 = le[e]; i0 = e; }
            int i1 = -1; float v1 = -INFINITY;
            #pragma unroll
            for (int e = 0; e < NEXP; e++)
                if (e != i0 && le[e] > v1) { v1 = le[e]; i1 = e; }

            // softmax over [v0, v1] with v0 = max
            float ex = __expf(v1 - v0);
            float g0 = 1.0f / (1.0f + ex);
            float g1 = ex * g0;

            *reinterpret_cast<float2*>(out_idx  + (size_t)tok * 2) =
                make_float2((float)i0, (float)i1);
            *reinterpret_cast<float2*>(out_gate + (size_t)tok * 2) =
                make_float2(g0, g1);
        }
    }
}

extern "C" void kernel_launch(void* const* d_in, const int* in_sizes, int n_in,
                              void* d_out, int out_size)
{
    const float* x = (const float*)d_in[0];
    const float* w = (const float*)d_in[1];
    float* out = (float*)d_out;

    const int n_tokens = in_sizes[0] / DDIM;     // 16384
    const int groups   = n_tokens / TGRP;        // 4096

    cudaFuncSetAttribute(router_kernel,
                         cudaFuncAttributeMaxDynamicSharedMemorySize,
                         SMEM_BYTES);

    router_kernel<<<NBLOCK, THREADS, SMEM_BYTES>>>(x, w, out, n_tokens, groups);
}